// round 11
// baseline (speedup 1.0000x reference)
#include <cuda_runtime.h>
#include <math.h>

#define BATCH 8
#define HH 720
#define WW 1280
#define HW (HH * WW)
#define NPIX (BATCH * HW)

#define CB 2                       // batches per chunk
#define NCHUNK (BATCH / CB)        // 4
#define CHUNK_PIX (CB * HW)        // 1,843,200

#define THREADS 256
#define SBLK (CHUNK_PIX / (2 * THREADS)) // 3600 scatter blocks / chunk (2 px/thr)
#define ZBLK (CHUNK_PIX / (2 * THREADS)) // 3600 zero blocks / chunk
#define NBLK (CHUNK_PIX / (2 * THREADS)) // 3600 norm blocks / chunk

// Full packed accumulator: (cnt, ox, oy, pad) per pixel.
__device__ float4 g_acc[NPIX];

__device__ __forceinline__ void red_add_v4(float4* addr, float a, float b, float c) {
    asm volatile(
        "red.global.add.v4.f32 [%0], {%1, %2, %3, %4};"
        :: "l"(addr), "f"(a), "f"(b), "f"(c), "f"(0.0f)
        : "memory");
}

// ---------------------------------------------------------------------------
// Per-pixel fallback: 4 unconditional corner reds (correct under clamping,
// since coincident corners just add twice, matching the reference).
// ---------------------------------------------------------------------------
__device__ __forceinline__ void scatter_one(int base, float x2, float y2,
                                            float d, float wx, float wy) {
    int xL = (int)floorf(x2);
    int yT = (int)floorf(y2);
    int xR = min(xL + 1, WW - 1);
    int yB = min(yT + 1, HH - 1);
    int rT = base + yT * WW;
    int rB = base + yB * WW;
    red_add_v4(&g_acc[rT + xL], d, wx, wy);
    red_add_v4(&g_acc[rT + xR], d, wx, wy);
    red_add_v4(&g_acc[rB + xL], d, wx, wy);
    red_add_v4(&g_acc[rB + xR], d, wx, wy);
}

// ---------------------------------------------------------------------------
// Scatter: one thread per horizontally adjacent source-pixel PAIR.
// Vectorized float2 input loads; register-merge of overlapping footprints.
// ---------------------------------------------------------------------------
__device__ __forceinline__ void do_scatter(int blk, int chunk,
                                           const float* __restrict__ flow,
                                           const float* __restrict__ depth) {
    int t = blk * THREADS + threadIdx.x;             // [0, CHUNK_PIX/2)
    int gi0 = chunk * CHUNK_PIX + 2 * t;             // even global pixel

    int b = gi0 / HW;
    int p0 = gi0 - b * HW;
    int y = p0 / WW;
    int x = p0 - y * WW;                             // even; pair in same row

    const float* fbase = flow + (size_t)b * 2 * HW;
    float2 fx = __ldcs(reinterpret_cast<const float2*>(fbase + p0));
    float2 fy = __ldcs(reinterpret_cast<const float2*>(fbase + HW + p0));
    float2 dd = __ldcs(reinterpret_cast<const float2*>(depth + gi0));

    float x20 = (float)x + fx.x,       y20 = (float)y + fy.x;
    float x21 = (float)(x + 1) + fx.y, y21 = (float)y + fy.y;

    bool v0 = (x20 >= 0.f) & (x20 <= (float)(WW - 1)) &
              (y20 >= 0.f) & (y20 <= (float)(HH - 1));
    bool v1 = (x21 >= 0.f) & (x21 <= (float)(WW - 1)) &
              (y21 >= 0.f) & (y21 <= (float)(HH - 1));
    if (!(v0 | v1)) return;

    float d0 = dd.x, wx0 = -fx.x * dd.x, wy0 = -fy.x * dd.x;
    float d1 = dd.y, wx1 = -fx.y * dd.y, wy1 = -fy.y * dd.y;
    int base = b * HW;

    if (v0 & v1) {
        int xL0 = (int)floorf(x20), yT0 = (int)floorf(y20);
        int xL1 = (int)floorf(x21), yT1 = (int)floorf(y21);
        int dx = xL1 - xL0;
        // Merged path: rows align, no clamping, dx in {0,1}.
        if (yT0 == yT1 && yT0 + 1 <= HH - 1 &&
            xL0 + 1 <= WW - 1 && xL1 + 1 <= WW - 1 &&
            (dx == 0 || dx == 1)) {
            int rT = base + yT0 * WW;
            int rB = rT + WW;
            float ds = d0 + d1, wxs = wx0 + wx1, wys = wy0 + wy1;
            if (dx == 0) {
                // Identical footprints: 4 reds for both pixels.
                red_add_v4(&g_acc[rT + xL0],     ds, wxs, wys);
                red_add_v4(&g_acc[rT + xL0 + 1], ds, wxs, wys);
                red_add_v4(&g_acc[rB + xL0],     ds, wxs, wys);
                red_add_v4(&g_acc[rB + xL0 + 1], ds, wxs, wys);
            } else {
                // Shared middle column: 6 reds.
                red_add_v4(&g_acc[rT + xL0],     d0, wx0, wy0);
                red_add_v4(&g_acc[rT + xL0 + 1], ds, wxs, wys);
                red_add_v4(&g_acc[rT + xL0 + 2], d1, wx1, wy1);
                red_add_v4(&g_acc[rB + xL0],     d0, wx0, wy0);
                red_add_v4(&g_acc[rB + xL0 + 1], ds, wxs, wys);
                red_add_v4(&g_acc[rB + xL0 + 2], d1, wx1, wy1);
            }
            return;
        }
        scatter_one(base, x20, y20, d0, wx0, wy0);
        scatter_one(base, x21, y21, d1, wx1, wy1);
        return;
    }
    if (v0) scatter_one(base, x20, y20, d0, wx0, wy0);
    else    scatter_one(base, x21, y21, d1, wx1, wy1);
}

__device__ __forceinline__ void do_zero(int blk, int chunk) {
    int t = blk * THREADS + threadIdx.x;             // [0, CHUNK_PIX/2)
    float4 z = make_float4(0.f, 0.f, 0.f, 0.f);
    int base = chunk * CHUNK_PIX;
    g_acc[base + t] = z;
    g_acc[base + t + CHUNK_PIX / 2] = z;
}

__device__ __forceinline__ void do_norm(int blk, int chunk,
                                        float* __restrict__ out) {
    int t = blk * THREADS + threadIdx.x;             // [0, CHUNK_PIX/2)
    int i0 = chunk * CHUNK_PIX + t;
    int i1 = i0 + CHUNK_PIX / 2;

    float4 a0 = g_acc[i0];
    float4 a1 = g_acc[i1];

    float ox0 = 0.f, oy0 = 0.f;
    if (a0.x > 0.f) { float inv = 1.f / a0.x; ox0 = a0.y * inv; oy0 = a0.z * inv; }
    float ox1 = 0.f, oy1 = 0.f;
    if (a1.x > 0.f) { float inv = 1.f / a1.x; ox1 = a1.y * inv; oy1 = a1.z * inv; }

    int b0 = i0 / HW, p0 = i0 - b0 * HW;
    int b1 = i1 / HW, p1 = i1 - b1 * HW;

    float* ob0 = out + (size_t)b0 * 2 * HW;
    float* ob1 = out + (size_t)b1 * 2 * HW;
    __stcs(ob0 + p0,      ox0);
    __stcs(ob0 + HW + p0, oy0);
    __stcs(ob1 + p1,      ox1);
    __stcs(ob1 + HW + p1, oy1);
}

// ---------------------------------------------------------------------------
// Striped fused kernels. SBLK == ZBLK == NBLK == 3600 now.
// mode 0: Z only.             mode 1: S+Z (stripe 2: 1S,1Z).
// mode 2: S+Z+N (stripe 3).   mode 3: S+N (stripe 2: 1S,1N).
// mode 4: N only.
// ---------------------------------------------------------------------------
__global__ void pipe_kernel(const float* __restrict__ flow,
                            const float* __restrict__ depth,
                            float* __restrict__ out,
                            int mode, int cS, int cZ, int cN) {
    int blk = blockIdx.x;
    if (mode == 0) {
        do_zero(blk, cZ);
    } else if (mode == 1) {
        int g = blk >> 1, r = blk & 1;
        if (r == 0) do_scatter(g, cS, flow, depth);
        else        do_zero(g, cZ);
    } else if (mode == 2) {
        int g = blk / 3, r = blk - g * 3;
        if (r == 0)      do_scatter(g, cS, flow, depth);
        else if (r == 1) do_zero(g, cZ);
        else             do_norm(g, cN, out);
    } else if (mode == 3) {
        int g = blk >> 1, r = blk & 1;
        if (r == 0) do_scatter(g, cS, flow, depth);
        else        do_norm(g, cN, out);
    } else {
        do_norm(blk, cN, out);
    }
}

extern "C" void kernel_launch(void* const* d_in, const int* in_sizes, int n_in,
                              void* d_out, int out_size) {
    const float* flow  = (const float*)d_in[0];   // (B, 2, H, W)
    const float* depth = (const float*)d_in[1];   // (B, 1, H, W)
    float* out = (float*)d_out;                   // (B, 2, H, W)

    (void)in_sizes; (void)n_in; (void)out_size;

    // Pipeline: Z0 | S0+Z1 | S1+Z2+N0 | S2+Z3+N1 | S3+N2 | N3
    pipe_kernel<<<ZBLK, THREADS>>>(flow, depth, out, 0, 0, 0, 0);
    pipe_kernel<<<SBLK + ZBLK, THREADS>>>(flow, depth, out, 1, 0, 1, 0);
    pipe_kernel<<<SBLK + ZBLK + NBLK, THREADS>>>(flow, depth, out, 2, 1, 2, 0);
    pipe_kernel<<<SBLK + ZBLK + NBLK, THREADS>>>(flow, depth, out, 2, 2, 3, 1);
    pipe_kernel<<<SBLK + NBLK, THREADS>>>(flow, depth, out, 3, 3, 0, 2);
    pipe_kernel<<<NBLK, THREADS>>>(flow, depth, out, 4, 0, 0, 3);
}